// round 13
// baseline (speedup 1.0000x reference)
#include <cuda_runtime.h>
#include <math.h>
#include <stdint.h>

#define N_NODES 50000
#define N_EDGES 800000
#define HEADS 4
#define HIDD 64
#define NCLS 47
#define NEG 0.2f
#define NBLK 49   // ceil(50000/1024)

// ---------------- static scratch (no allocations allowed) ----------------
__device__ __align__(256) float g_bufA[N_NODES * 256];
__device__ __align__(256) float g_bufB[N_NODES * 256];
__device__ __align__(256) float g_h2[N_NODES * NCLS];
__device__ float g_el[N_NODES * HEADS];
__device__ float g_er[N_NODES * HEADS];
__device__ int   g_cnt[N_NODES];
__device__ int   g_rowptr[N_NODES + 1];
__device__ int   g_bsum[NBLK];
__device__ int   g_esrc[N_EDGES];

#define BUF_A   0
#define BUF_B   1
#define BUF_H2  2
#define BUF_EXT 3

__device__ __forceinline__ float* sel_buf(int sel, float* ext) {
    switch (sel) {
        case BUF_A:  return g_bufA;
        case BUF_B:  return g_bufB;
        case BUF_H2: return g_h2;
        default:     return ext;
    }
}

// ---------------- CSR build (dst-sorted edge list) ----------------
__global__ void zero_cnt_k() {
    int i = blockIdx.x * blockDim.x + threadIdx.x;
    if (i < N_NODES) g_cnt[i] = 0;
}

__global__ void hist_k(const int* __restrict__ dst) {
    int e = blockIdx.x * blockDim.x + threadIdx.x;
    if (e < N_EDGES) atomicAdd(&g_cnt[dst[e]], 1);
}

__global__ void scan1_k() {
    __shared__ int s[1024];
    int b = blockIdx.x, tid = threadIdx.x;
    int i = b * 1024 + tid;
    int v = (i < N_NODES) ? g_cnt[i] : 0;
    s[tid] = v;
    __syncthreads();
    #pragma unroll
    for (int off = 1; off < 1024; off <<= 1) {
        int t = (tid >= off) ? s[tid - off] : 0;
        __syncthreads();
        s[tid] += t;
        __syncthreads();
    }
    if (i < N_NODES) g_rowptr[i + 1] = s[tid];
    if (tid == 1023) g_bsum[b] = s[1023];
}

__global__ void scan2_k() {
    __shared__ int s[64];
    int tid = threadIdx.x;
    int v = (tid < NBLK) ? g_bsum[tid] : 0;
    s[tid] = v;
    __syncthreads();
    #pragma unroll
    for (int off = 1; off < 64; off <<= 1) {
        int t = (tid >= off) ? s[tid - off] : 0;
        __syncthreads();
        s[tid] += t;
        __syncthreads();
    }
    if (tid < NBLK) g_bsum[tid] = s[tid] - v;   // exclusive
}

__global__ void scan3_k() {
    int b = blockIdx.x, tid = threadIdx.x;
    int i = b * 1024 + tid;
    if (i < N_NODES) {
        g_rowptr[i + 1] += g_bsum[b];
        g_cnt[i] = 0;
    }
    if (b == 0 && tid == 0) g_rowptr[0] = 0;
}

__global__ void scatter_k(const int* __restrict__ src, const int* __restrict__ dst) {
    int e = blockIdx.x * blockDim.x + threadIdx.x;
    if (e < N_EDGES) {
        int d = dst[e];
        int pos = g_rowptr[d] + atomicAdd(&g_cnt[d], 1);
        g_esrc[pos] = src[e];
    }
}

// ---------------- tensor-core GEMM + fused el/er epilogue ----------------
// C[n,m] = A[n,256] @ B[256,m], 3xTF32, split at fragment read (R6 numerics).
// NEW: (k,k+4) pairs stored as adjacent float2 in smem -> LDS.64 fragment
// loads (8 per ks-step vs 16 LDS.32, same bytes). A uses XOR swizzle
// p' = p ^ 6*row[1] ^ row[2] (LDS + STS both conflict-free). 3-stage smem,
// ONE __syncthreads per tile, reg-staged LDG prefetch distance 1.
// Block 128x64, 8 warps (4x2), warp 32x32, BK=16.

__device__ __forceinline__ void cvt_split_u(float x, uint32_t& hi, uint32_t& lo) {
    uint32_t h;
    asm("cvt.rna.tf32.f32 %0, %1;" : "=r"(h) : "f"(x));
    hi = h;
    lo = __float_as_uint(x - __uint_as_float(h));
}

__device__ __forceinline__ void mma8(float* c, const uint32_t* a, const uint32_t* b) {
    asm volatile(
        "mma.sync.aligned.m16n8k8.row.col.f32.tf32.tf32.f32 "
        "{%0,%1,%2,%3}, {%4,%5,%6,%7}, {%8,%9}, {%0,%1,%2,%3};"
        : "+f"(c[0]), "+f"(c[1]), "+f"(c[2]), "+f"(c[3])
        : "r"(a[0]), "r"(a[1]), "r"(a[2]), "r"(a[3]), "r"(b[0]), "r"(b[1]));
}

__global__ void __launch_bounds__(256, 2)
gemm_mma_k(const float* __restrict__ Aext, int selA, int selC,
           const float* __restrict__ B, int m,
           const float* __restrict__ alv, const float* __restrict__ arv, int H) {
    const float* A = (selA == BUF_EXT) ? Aext : (const float*)sel_buf(selA, nullptr);
    float* C = sel_buf(selC, nullptr);

    __shared__ float2 As3[3][128][8];   // [row][p'] swizzled pairs; stride 16 words
    __shared__ float2 Bs3[3][8][68];    // [pr][col] pairs; stride 136 words
    __shared__ float els[128], ers[128];

    int t = threadIdx.x;
    int warp = t >> 5, lane = t & 31;
    int wm = warp >> 1, wn = warp & 1;
    int g = lane >> 2, tq = lane & 3;
    int rowBlk = blockIdx.y * 128;
    int hd = blockIdx.x;
    int colBlk = hd * 64;

    float c[2][4][4] = {};
    float a_st[8], b_st[4];

    // A loader: row = t>>1, k-half = t&1 (8 consecutive k)
    int larow = t >> 1;
    int lksb  = t & 1;
    int lswz  = (6 * ((larow >> 1) & 1)) ^ ((larow >> 2) & 1);
    // B loader: col = t&63, k quarter = t>>6 (4 consecutive k)
    int lbcol = t & 63;
    int lbkq  = t >> 6;

    // fragment-read swizzle (row bits 1,2 come from g only)
    int swz_a = (6 * ((g >> 1) & 1)) ^ ((g >> 2) & 1);
    int pA0 = tq ^ swz_a;          // ksb=0
    int pA1 = (4 + tq) ^ swz_a;    // ksb=1

    #define LDA(kt)                                                                \
    {                                                                              \
        int row = rowBlk + larow;                                                  \
        if (row < N_NODES) {                                                       \
            const float* ap = A + (size_t)row * 256 + (kt) + lksb * 8;             \
            float4 v0 = *(const float4*)ap;                                        \
            float4 v1 = *(const float4*)(ap + 4);                                  \
            a_st[0]=v0.x; a_st[1]=v0.y; a_st[2]=v0.z; a_st[3]=v0.w;                \
            a_st[4]=v1.x; a_st[5]=v1.y; a_st[6]=v1.z; a_st[7]=v1.w;                \
        } else {                                                                   \
            _Pragma("unroll") for (int i_ = 0; i_ < 8; i_++) a_st[i_] = 0.f;       \
        }                                                                          \
    }

    #define LDB(kt)                                                                \
    {                                                                              \
        int col = colBlk + lbcol;                                                  \
        _Pragma("unroll")                                                          \
        for (int p = 0; p < 4; p++) {                                              \
            b_st[p] = (col < m) ? B[(size_t)((kt) + lbkq * 4 + p) * m + col] : 0.f;\
        }                                                                          \
    }

    #define STS_AB(s)                                                              \
    {                                                                              \
        _Pragma("unroll")                                                          \
        for (int j = 0; j < 4; j++) {                                              \
            As3[s][larow][(lksb * 4 + j) ^ lswz] =                                 \
                make_float2(a_st[j], a_st[j + 4]);                                 \
        }                                                                          \
        _Pragma("unroll")                                                          \
        for (int p = 0; p < 4; p++) {                                              \
            float* dp = &Bs3[s][(lbkq >> 1) * 4 + p][lbcol].x;                     \
            dp[lbkq & 1] = b_st[p];                                                \
        }                                                                          \
    }

    // prologue: tile0 -> stage0; tile1 held in regs
    LDA(0); LDB(0);
    STS_AB(0);
    LDA(16); LDB(16);

    int sW = 1;   // stage to write next (tile i+1 at iter i)
    for (int i = 0; i < 16; i++) {
        int sR = (i == 0) ? 0 : ((sW + 1) % 3);   // stage holding tile i
        // precise: tile i lives in stage i%3; track directly:
        sR = i - (i / 3) * 3;
        if (i < 15) {
            int sw = (i + 1) % 3;
            STS_AB(sw);
        }
        if (i < 14) { LDA((i + 2) * 16); LDB((i + 2) * 16); }
        __syncthreads();

        #pragma unroll
        for (int ksb = 0; ksb < 2; ksb++) {
            int pA = ksb ? pA1 : pA0;
            int prb = ksb * 4 + tq;
            uint32_t bh[4][2], bl[4][2];
            #pragma unroll
            for (int nt = 0; nt < 4; nt++) {
                int col = wn * 32 + nt * 8 + g;
                float2 bv = Bs3[sR][prb][col];
                cvt_split_u(bv.x, bh[nt][0], bl[nt][0]);
                cvt_split_u(bv.y, bh[nt][1], bl[nt][1]);
            }
            #pragma unroll
            for (int mt = 0; mt < 2; mt++) {
                int r0 = wm * 32 + mt * 16 + g;
                float2 av0 = As3[sR][r0][pA];
                float2 av1 = As3[sR][r0 + 8][pA];
                uint32_t ah[4], al_[4];
                cvt_split_u(av0.x, ah[0], al_[0]);
                cvt_split_u(av1.x, ah[1], al_[1]);
                cvt_split_u(av0.y, ah[2], al_[2]);
                cvt_split_u(av1.y, ah[3], al_[3]);
                #pragma unroll
                for (int nt = 0; nt < 4; nt++) {
                    mma8(c[mt][nt], ah,  bh[nt]);
                    mma8(c[mt][nt], ah,  bl[nt]);
                    mma8(c[mt][nt], al_, bh[nt]);
                }
            }
        }
        (void)sW;
    }

    // store C
    #pragma unroll
    for (int mt = 0; mt < 2; mt++) {
        #pragma unroll
        for (int nt = 0; nt < 4; nt++) {
            int row = rowBlk + wm * 32 + mt * 16 + g;
            int col = colBlk + wn * 32 + nt * 8 + tq * 2;
            if (row < N_NODES) {
                if (col < m)     C[(size_t)row * m + col]     = c[mt][nt][0];
                if (col + 1 < m) C[(size_t)row * m + col + 1] = c[mt][nt][1];
            }
            if (row + 8 < N_NODES) {
                if (col < m)     C[(size_t)(row + 8) * m + col]     = c[mt][nt][2];
                if (col + 1 < m) C[(size_t)(row + 8) * m + col + 1] = c[mt][nt][3];
            }
        }
    }

    // fused el/er epilogue
    if (t < 128) { els[t] = 0.f; ers[t] = 0.f; }
    __syncthreads();
    #pragma unroll
    for (int mt = 0; mt < 2; mt++) {
        float pe0 = 0.f, pr0 = 0.f, pe1 = 0.f, pr1 = 0.f;
        #pragma unroll
        for (int nt = 0; nt < 4; nt++) {
            #pragma unroll
            for (int j = 0; j < 2; j++) {
                int colg = colBlk + wn * 32 + nt * 8 + tq * 2 + j;
                float av = (colg < m) ? alv[colg] : 0.f;
                float rv = (colg < m) ? arv[colg] : 0.f;
                pe0 += c[mt][nt][j] * av;     pr0 += c[mt][nt][j] * rv;
                pe1 += c[mt][nt][2 + j] * av; pr1 += c[mt][nt][2 + j] * rv;
            }
        }
        #pragma unroll
        for (int off = 1; off <= 2; off <<= 1) {
            pe0 += __shfl_xor_sync(0xffffffffu, pe0, off);
            pr0 += __shfl_xor_sync(0xffffffffu, pr0, off);
            pe1 += __shfl_xor_sync(0xffffffffu, pe1, off);
            pr1 += __shfl_xor_sync(0xffffffffu, pr1, off);
        }
        if (tq == 0) {
            int rl = wm * 32 + mt * 16 + g;
            atomicAdd(&els[rl], pe0);     atomicAdd(&ers[rl], pr0);
            atomicAdd(&els[rl + 8], pe1); atomicAdd(&ers[rl + 8], pr1);
        }
    }
    __syncthreads();
    if (t < 128) {
        int row = rowBlk + t;
        if (row < N_NODES) {
            g_el[row * H + hd] = els[t];
            g_er[row * H + hd] = ers[t];
        }
    }
}

// ---------------- D=64 agg: float2 gather, unroll-4 broadcast -------------
template <int H>
__global__ void agg64_k(int selH, int selOut, const float* __restrict__ bias) {
    const float2* hb = (const float2*)sel_buf(selH, nullptr);
    float2* ob = (float2*)sel_buf(selOut, nullptr);
    int w = (blockIdx.x * blockDim.x + threadIdx.x) >> 5;
    int lane = threadIdx.x & 31;
    if (w >= N_NODES * H) return;
    int n = w / H, hd = w % H;
    int beg = g_rowptr[n], end = g_rowptr[n + 1];
    int deg = end - beg;

    const float2* bias2 = (const float2*)bias;
    float2 bv = bias2[hd * 32 + lane];
    size_t obase = (size_t)n * (H * 32) + hd * 32 + lane;

    if (deg == 0) { ob[obase] = bv; return; }

    float ern = g_er[n * H + hd];

    float mx = -INFINITY;
    int   cs = 0;
    float ce = -INFINITY;
    for (int j0 = 0; j0 < deg; j0 += 32) {
        int j = j0 + lane;
        if (j < deg) {
            int s = g_esrc[beg + j];
            float e = g_el[s * H + hd] + ern;
            e = (e > 0.f) ? e : NEG * e;
            if (j0 == 0) { cs = s; ce = e; }
            mx = fmaxf(mx, e);
        }
    }
    #pragma unroll
    for (int off = 16; off > 0; off >>= 1)
        mx = fmaxf(mx, __shfl_xor_sync(0xffffffffu, mx, off));

    float den = 0.f, ax = 0.f, ay = 0.f;
    for (int j0 = 0; j0 < deg; j0 += 32) {
        int j = j0 + lane;
        int s_l = cs;
        float e_l = ce;
        if (j0 > 0) {
            s_l = 0; e_l = -INFINITY;
            if (j < deg) {
                s_l = g_esrc[beg + j];
                float e = g_el[s_l * H + hd] + ern;
                e_l = (e > 0.f) ? e : NEG * e;
            }
        }
        float w_l = (j < deg) ? __expf(e_l - mx) : 0.f;
        den += w_l;
        int cnt = min(32, deg - j0);
        int j2 = 0;
        for (; j2 + 4 <= cnt; j2 += 4) {
            int s0 = __shfl_sync(0xffffffffu, s_l, j2);
            int s1 = __shfl_sync(0xffffffffu, s_l, j2 + 1);
            int s2 = __shfl_sync(0xffffffffu, s_l, j2 + 2);
            int s3 = __shfl_sync(0xffffffffu, s_l, j2 + 3);
            float w0 = __shfl_sync(0xffffffffu, w_l, j2);
            float w1 = __shfl_sync(0xffffffffu, w_l, j2 + 1);
            float w2 = __shfl_sync(0xffffffffu, w_l, j2 + 2);
            float w3 = __shfl_sync(0xffffffffu, w_l, j2 + 3);
            float2 v0 = hb[(size_t)s0 * (H * 32) + hd * 32 + lane];
            float2 v1 = hb[(size_t)s1 * (H * 32) + hd * 32 + lane];
            float2 v2 = hb[(size_t)s2 * (H * 32) + hd * 32 + lane];
            float2 v3 = hb[(size_t)s3 * (H * 32) + hd * 32 + lane];
            ax += w0 * v0.x; ay += w0 * v0.y;
            ax += w1 * v1.x; ay += w1 * v1.y;
            ax += w2 * v2.x; ay += w2 * v2.y;
            ax += w3 * v3.x; ay += w3 * v3.y;
        }
        for (; j2 < cnt; j2++) {
            int sj = __shfl_sync(0xffffffffu, s_l, j2);
            float wj = __shfl_sync(0xffffffffu, w_l, j2);
            float2 v = hb[(size_t)sj * (H * 32) + hd * 32 + lane];
            ax += wj * v.x; ay += wj * v.y;
        }
    }
    #pragma unroll
    for (int off = 16; off > 0; off >>= 1)
        den += __shfl_xor_sync(0xffffffffu, den, off);
    float inv = 1.0f / den;

    float2 o;
    o.x = ax * inv + bv.x;
    o.y = ay * inv + bv.y;
    ob[obase] = o;
}

// ---------------- generic agg (layer 2: H=1, D=47) -----------------------
template <int H, int D>
__global__ void agg_k(int selH, int selOut,
                      const float* __restrict__ bias,
                      float* __restrict__ out_ext) {
    const float* hbuf = sel_buf(selH, nullptr);
    float* out = sel_buf(selOut, out_ext);
    int w = (blockIdx.x * blockDim.x + threadIdx.x) >> 5;
    int lane = threadIdx.x & 31;
    if (w >= N_NODES * H) return;
    int n = w / H, hd = w % H;
    int beg = g_rowptr[n], end = g_rowptr[n + 1];
    int deg = end - beg;

    const int c0 = hd * D + lane;
    const int c1 = hd * D + lane + 32;

    if (deg == 0) {
        if (lane < D)                out[(size_t)n * (H * D) + c0] = bias[c0];
        if (D > 32 && lane + 32 < D) out[(size_t)n * (H * D) + c1] = bias[c1];
        return;
    }

    float ern = g_er[n * H + hd];

    float mx = -INFINITY;
    int   cs = 0;
    float ce = -INFINITY;
    for (int j0 = 0; j0 < deg; j0 += 32) {
        int j = j0 + lane;
        if (j < deg) {
            int s = g_esrc[beg + j];
            float e = g_el[s * H + hd] + ern;
            e = (e > 0.f) ? e : NEG * e;
            if (j0 == 0) { cs = s; ce = e; }
            mx = fmaxf(mx, e);
        }
    }
    #pragma unroll
    for (int off = 16; off > 0; off >>= 1)
        mx = fmaxf(mx, __shfl_xor_sync(0xffffffffu, mx, off));

    float den = 0.f, acc0 = 0.f, acc1 = 0.f;
    for (int j0 = 0; j0 < deg; j0 += 32) {
        int j = j0 + lane;
        int s_l = cs;
        float e_l = ce;
        if (j0 > 0) {
            s_l = 0; e_l = -INFINITY;
            if (j < deg) {
                s_l = g_esrc[beg + j];
                float e = g_el[s_l * H + hd] + ern;
                e_l = (e > 0.f) ? e : NEG * e;
            }
        }
        float w_l = (j < deg) ? __expf(e_l - mx) : 0.f;
        den += w_l;
        int cnt = min(32, deg - j0);
        for (int j2 = 0; j2 < cnt; j2++) {
            float wj = __shfl_sync(0xffffffffu, w_l, j2);
            int   sj = __shfl_sync(0xffffffffu, s_l, j2);
            const float* hs = hbuf + (size_t)sj * (H * D) + hd * D;
            if (lane < D)                acc0 += wj * hs[lane];
            if (D > 32 && lane + 32 < D) acc1 += wj * hs[lane + 32];
        }
    }
    #pragma unroll
    for (int off = 16; off > 0; off >>= 1)
        den += __shfl_xor_sync(0xffffffffu, den, off);
    float inv = 1.0f / den;

    if (lane < D)                out[(size_t)n * (H * D) + c0] = acc0 * inv + bias[c0];
    if (D > 32 && lane + 32 < D) out[(size_t)n * (H * D) + c1] = acc1 * inv + bias[c1];
}

// ---------------- launch (nothing but kernel launches here) ----------------
extern "C" void kernel_launch(void* const* d_in, const int* in_sizes, int n_in,
                              void* d_out, int out_size) {
    const float* x   = (const float*)d_in[0];
    const int*   src = (const int*)d_in[1];
    const int*   dst = (const int*)d_in[2];
    const float* W0  = (const float*)d_in[3];
    const float* al0 = (const float*)d_in[4];
    const float* ar0 = (const float*)d_in[5];
    const float* b0  = (const float*)d_in[6];
    const float* W1  = (const float*)d_in[7];
    const float* al1 = (const float*)d_in[8];
    const float* ar1 = (const float*)d_in[9];
    const float* b1  = (const float*)d_in[10];
    const float* W2  = (const float*)d_in[11];
    const float* al2 = (const float*)d_in[12];
    const float* ar2 = (const float*)d_in[13];
    const float* b2  = (const float*)d_in[14];
    float* out = (float*)d_out;

    const int ZB = (N_NODES + 255) / 256;
    const int EB = (N_EDGES + 255) / 256;
    const int WB4 = (N_NODES * HEADS * 32 + 255) / 256;
    const int WB1 = (N_NODES * 1 * 32 + 255) / 256;

    dim3 g256(4, (N_NODES + 127) / 128);
    dim3 g47(1, (N_NODES + 127) / 128);

    // Slot 3 (0-based) gets profiled by ncu -> layer-0 GEMM stays there.
    zero_cnt_k<<<ZB, 256>>>();                                              // 0
    hist_k<<<EB, 256>>>(dst);                                               // 1
    scan1_k<<<NBLK, 1024>>>();                                              // 2
    gemm_mma_k<<<g256, 256>>>(x, BUF_EXT, BUF_A, W0, 256, al0, ar0, HEADS); // 3 (profiled)
    scan2_k<<<1, 64>>>();                                                   // 4
    scan3_k<<<NBLK, 1024>>>();                                              // 5
    scatter_k<<<EB, 256>>>(src, dst);                                       // 6

    // layer 0 aggregation
    agg64_k<HEADS><<<WB4, 256>>>(BUF_A, BUF_B, b0);
    // layer 1
    gemm_mma_k<<<g256, 256>>>(nullptr, BUF_B, BUF_A, W1, 256, al1, ar1, HEADS);
    agg64_k<HEADS><<<WB4, 256>>>(BUF_A, BUF_B, b1);
    // layer 2 (1 head, 47 classes)
    gemm_mma_k<<<g47, 256>>>(nullptr, BUF_B, BUF_H2, W2, NCLS, al2, ar2, 1);
    agg_k<1, NCLS><<<WB1, 256>>>(BUF_H2, BUF_EXT, b2, out);
}

// round 14
// speedup vs baseline: 1.0605x; 1.0605x over previous
#include <cuda_runtime.h>
#include <math.h>
#include <stdint.h>

#define N_NODES 50000
#define N_EDGES 800000
#define HEADS 4
#define HIDD 64
#define NCLS 47
#define NEG 0.2f
#define NBLK 49   // ceil(50000/1024)

// ---------------- static scratch (no allocations allowed) ----------------
__device__ __align__(256) float g_bufA[N_NODES * 256];
__device__ __align__(256) float g_bufB[N_NODES * 256];
__device__ __align__(256) float g_h2[N_NODES * NCLS];
__device__ float g_el[N_NODES * HEADS];
__device__ float g_er[N_NODES * HEADS];
__device__ int   g_cnt[N_NODES];
__device__ int   g_rowptr[N_NODES + 1];
__device__ int   g_bsum[NBLK];
__device__ int   g_esrc[N_EDGES];

#define BUF_A   0
#define BUF_B   1
#define BUF_H2  2
#define BUF_EXT 3

__device__ __forceinline__ float* sel_buf(int sel, float* ext) {
    switch (sel) {
        case BUF_A:  return g_bufA;
        case BUF_B:  return g_bufB;
        case BUF_H2: return g_h2;
        default:     return ext;
    }
}

// ---------------- CSR build (dst-sorted edge list) ----------------
__global__ void zero_cnt_k() {
    int i = blockIdx.x * blockDim.x + threadIdx.x;
    if (i < N_NODES) g_cnt[i] = 0;
}

__global__ void hist_k(const int* __restrict__ dst) {
    int e = blockIdx.x * blockDim.x + threadIdx.x;
    if (e < N_EDGES) atomicAdd(&g_cnt[dst[e]], 1);
}

__global__ void scan1_k() {
    __shared__ int s[1024];
    int b = blockIdx.x, tid = threadIdx.x;
    int i = b * 1024 + tid;
    int v = (i < N_NODES) ? g_cnt[i] : 0;
    s[tid] = v;
    __syncthreads();
    #pragma unroll
    for (int off = 1; off < 1024; off <<= 1) {
        int t = (tid >= off) ? s[tid - off] : 0;
        __syncthreads();
        s[tid] += t;
        __syncthreads();
    }
    if (i < N_NODES) g_rowptr[i + 1] = s[tid];
    if (tid == 1023) g_bsum[b] = s[1023];
}

__global__ void scan2_k() {
    __shared__ int s[64];
    int tid = threadIdx.x;
    int v = (tid < NBLK) ? g_bsum[tid] : 0;
    s[tid] = v;
    __syncthreads();
    #pragma unroll
    for (int off = 1; off < 64; off <<= 1) {
        int t = (tid >= off) ? s[tid - off] : 0;
        __syncthreads();
        s[tid] += t;
        __syncthreads();
    }
    if (tid < NBLK) g_bsum[tid] = s[tid] - v;   // exclusive
}

__global__ void scan3_k() {
    int b = blockIdx.x, tid = threadIdx.x;
    int i = b * 1024 + tid;
    if (i < N_NODES) {
        g_rowptr[i + 1] += g_bsum[b];
        g_cnt[i] = 0;
    }
    if (b == 0 && tid == 0) g_rowptr[0] = 0;
}

__global__ void scatter_k(const int* __restrict__ src, const int* __restrict__ dst) {
    int e = blockIdx.x * blockDim.x + threadIdx.x;
    if (e < N_EDGES) {
        int d = dst[e];
        int pos = g_rowptr[d] + atomicAdd(&g_cnt[d], 1);
        g_esrc[pos] = src[e];
    }
}

// ---------------- tensor-core GEMM + fused el/er epilogue ----------------
// EXACT R6/R12 structure except MMA issue order: all 8 independent hh MMAs,
// then 8 hl, then 8 lh -> dependent MMAs on the same accumulator are 8 apart
// instead of adjacent (asm volatile blocks ptxas reordering). Per-accumulator
// order unchanged (hh,hl,lh) -> bitwise-identical numerics.

__device__ __forceinline__ void cvt_split_u(float x, uint32_t& hi, uint32_t& lo) {
    uint32_t h;
    asm("cvt.rna.tf32.f32 %0, %1;" : "=r"(h) : "f"(x));
    hi = h;
    lo = __float_as_uint(x - __uint_as_float(h));
}

__device__ __forceinline__ void mma8(float* c, const uint32_t* a, const uint32_t* b) {
    asm volatile(
        "mma.sync.aligned.m16n8k8.row.col.f32.tf32.tf32.f32 "
        "{%0,%1,%2,%3}, {%4,%5,%6,%7}, {%8,%9}, {%0,%1,%2,%3};"
        : "+f"(c[0]), "+f"(c[1]), "+f"(c[2]), "+f"(c[3])
        : "r"(a[0]), "r"(a[1]), "r"(a[2]), "r"(a[3]), "r"(b[0]), "r"(b[1]));
}

__device__ __forceinline__ void cp16(uint32_t dst, const float* src, int sz) {
    asm volatile("cp.async.cg.shared.global [%0], [%1], 16, %2;\n"
                 :: "r"(dst), "l"(src), "r"(sz));
}
__device__ __forceinline__ void cp4(uint32_t dst, const float* src, int sz) {
    asm volatile("cp.async.ca.shared.global [%0], [%1], 4, %2;\n"
                 :: "r"(dst), "l"(src), "r"(sz));
}

__global__ void __launch_bounds__(256, 2)
gemm_mma_k(const float* __restrict__ Aext, int selA, int selC,
           const float* __restrict__ B, int m,
           const float* __restrict__ alv, const float* __restrict__ arv, int H) {
    const float* A = (selA == BUF_EXT) ? Aext : (const float*)sel_buf(selA, nullptr);
    float* C = sel_buf(selC, nullptr);

    __shared__ float As[2][128][20];
    __shared__ float Bs[2][16][72];
    __shared__ float els[128], ers[128];

    int t = threadIdx.x;
    int warp = t >> 5, lane = t & 31;
    int wm = warp >> 1, wn = warp & 1;
    int g = lane >> 2, tq = lane & 3;
    int rowBlk = blockIdx.y * 128;
    int hd = blockIdx.x;
    int colBlk = hd * 64;

    float c[2][4][4] = {};

    int ar0_ = t >> 2;
    int ak0_ = (t & 3) * 4;
    int ar1_ = (t + 256) >> 2;
    int ak1_ = ak0_;
    int bkb = t >> 4, bcc = (t & 15) * 4;

    #define PREFETCH(kt, buf)                                                      \
    {                                                                              \
        int rA0 = rowBlk + ar0_, rA1 = rowBlk + ar1_;                              \
        cp16((uint32_t)__cvta_generic_to_shared(&As[buf][ar0_][ak0_]),             \
             A + (size_t)min(rA0, N_NODES - 1) * 256 + (kt) + ak0_,                \
             rA0 < N_NODES ? 16 : 0);                                              \
        cp16((uint32_t)__cvta_generic_to_shared(&As[buf][ar1_][ak1_]),             \
             A + (size_t)min(rA1, N_NODES - 1) * 256 + (kt) + ak1_,                \
             rA1 < N_NODES ? 16 : 0);                                              \
        if (m == 256) {                                                            \
            cp16((uint32_t)__cvta_generic_to_shared(&Bs[buf][bkb][bcc]),           \
                 B + (size_t)((kt) + bkb) * 256 + colBlk + bcc, 16);               \
        } else {                                                                   \
            _Pragma("unroll")                                                      \
            for (int p = 0; p < 4; p++) {                                          \
                int id = t + p * 256;                                              \
                int kb = id >> 6, cc = id & 63;                                    \
                int col = colBlk + cc;                                             \
                cp4((uint32_t)__cvta_generic_to_shared(&Bs[buf][kb][cc]),          \
                    B + (size_t)((kt) + kb) * m + min(col, m - 1),                 \
                    col < m ? 4 : 0);                                              \
            }                                                                      \
        }                                                                          \
        asm volatile("cp.async.commit_group;\n");                                  \
    }

    PREFETCH(0, 0);

    for (int i = 0; i < 16; i++) {
        int buf = i & 1;
        if (i < 15) {
            PREFETCH((i + 1) * 16, buf ^ 1);
            asm volatile("cp.async.wait_group 1;\n");
        } else {
            asm volatile("cp.async.wait_group 0;\n");
        }
        __syncthreads();

        #pragma unroll
        for (int ks = 0; ks < 16; ks += 8) {
            uint32_t bh[4][2], bl[4][2];
            #pragma unroll
            for (int nt = 0; nt < 4; nt++) {
                int col = wn * 32 + nt * 8 + g;
                cvt_split_u(Bs[buf][ks + tq][col],     bh[nt][0], bl[nt][0]);
                cvt_split_u(Bs[buf][ks + tq + 4][col], bh[nt][1], bl[nt][1]);
            }
            uint32_t ah[2][4], al_[2][4];
            #pragma unroll
            for (int mt = 0; mt < 2; mt++) {
                int r0 = wm * 32 + mt * 16 + g;
                cvt_split_u(As[buf][r0][ks + tq],         ah[mt][0], al_[mt][0]);
                cvt_split_u(As[buf][r0 + 8][ks + tq],     ah[mt][1], al_[mt][1]);
                cvt_split_u(As[buf][r0][ks + tq + 4],     ah[mt][2], al_[mt][2]);
                cvt_split_u(As[buf][r0 + 8][ks + tq + 4], ah[mt][3], al_[mt][3]);
            }
            // term-major issue: dependent MMAs on same c are 8 apart
            #pragma unroll
            for (int mt = 0; mt < 2; mt++)
                #pragma unroll
                for (int nt = 0; nt < 4; nt++)
                    mma8(c[mt][nt], ah[mt],  bh[nt]);
            #pragma unroll
            for (int mt = 0; mt < 2; mt++)
                #pragma unroll
                for (int nt = 0; nt < 4; nt++)
                    mma8(c[mt][nt], ah[mt],  bl[nt]);
            #pragma unroll
            for (int mt = 0; mt < 2; mt++)
                #pragma unroll
                for (int nt = 0; nt < 4; nt++)
                    mma8(c[mt][nt], al_[mt], bh[nt]);
        }
        __syncthreads();
    }

    #pragma unroll
    for (int mt = 0; mt < 2; mt++) {
        #pragma unroll
        for (int nt = 0; nt < 4; nt++) {
            int row = rowBlk + wm * 32 + mt * 16 + g;
            int col = colBlk + wn * 32 + nt * 8 + tq * 2;
            if (row < N_NODES) {
                if (col < m)     C[(size_t)row * m + col]     = c[mt][nt][0];
                if (col + 1 < m) C[(size_t)row * m + col + 1] = c[mt][nt][1];
            }
            if (row + 8 < N_NODES) {
                if (col < m)     C[(size_t)(row + 8) * m + col]     = c[mt][nt][2];
                if (col + 1 < m) C[(size_t)(row + 8) * m + col + 1] = c[mt][nt][3];
            }
        }
    }

    // fused el/er epilogue
    if (t < 128) { els[t] = 0.f; ers[t] = 0.f; }
    __syncthreads();
    #pragma unroll
    for (int mt = 0; mt < 2; mt++) {
        float pe0 = 0.f, pr0 = 0.f, pe1 = 0.f, pr1 = 0.f;
        #pragma unroll
        for (int nt = 0; nt < 4; nt++) {
            #pragma unroll
            for (int j = 0; j < 2; j++) {
                int colg = colBlk + wn * 32 + nt * 8 + tq * 2 + j;
                float av = (colg < m) ? alv[colg] : 0.f;
                float rv = (colg < m) ? arv[colg] : 0.f;
                pe0 += c[mt][nt][j] * av;     pr0 += c[mt][nt][j] * rv;
                pe1 += c[mt][nt][2 + j] * av; pr1 += c[mt][nt][2 + j] * rv;
            }
        }
        #pragma unroll
        for (int off = 1; off <= 2; off <<= 1) {
            pe0 += __shfl_xor_sync(0xffffffffu, pe0, off);
            pr0 += __shfl_xor_sync(0xffffffffu, pr0, off);
            pe1 += __shfl_xor_sync(0xffffffffu, pe1, off);
            pr1 += __shfl_xor_sync(0xffffffffu, pr1, off);
        }
        if (tq == 0) {
            int rl = wm * 32 + mt * 16 + g;
            atomicAdd(&els[rl], pe0);     atomicAdd(&ers[rl], pr0);
            atomicAdd(&els[rl + 8], pe1); atomicAdd(&ers[rl + 8], pr1);
        }
    }
    __syncthreads();
    if (t < 128) {
        int row = rowBlk + t;
        if (row < N_NODES) {
            g_el[row * H + hd] = els[t];
            g_er[row * H + hd] = ers[t];
        }
    }
}

// ---------------- D=64 agg: float2 gather, unroll-4 broadcast -------------
template <int H>
__global__ void agg64_k(int selH, int selOut, const float* __restrict__ bias) {
    const float2* hb = (const float2*)sel_buf(selH, nullptr);
    float2* ob = (float2*)sel_buf(selOut, nullptr);
    int w = (blockIdx.x * blockDim.x + threadIdx.x) >> 5;
    int lane = threadIdx.x & 31;
    if (w >= N_NODES * H) return;
    int n = w / H, hd = w % H;
    int beg = g_rowptr[n], end = g_rowptr[n + 1];
    int deg = end - beg;

    const float2* bias2 = (const float2*)bias;
    float2 bv = bias2[hd * 32 + lane];
    size_t obase = (size_t)n * (H * 32) + hd * 32 + lane;

    if (deg == 0) { ob[obase] = bv; return; }

    float ern = g_er[n * H + hd];

    float mx = -INFINITY;
    int   cs = 0;
    float ce = -INFINITY;
    for (int j0 = 0; j0 < deg; j0 += 32) {
        int j = j0 + lane;
        if (j < deg) {
            int s = g_esrc[beg + j];
            float e = g_el[s * H + hd] + ern;
            e = (e > 0.f) ? e : NEG * e;
            if (j0 == 0) { cs = s; ce = e; }
            mx = fmaxf(mx, e);
        }
    }
    #pragma unroll
    for (int off = 16; off > 0; off >>= 1)
        mx = fmaxf(mx, __shfl_xor_sync(0xffffffffu, mx, off));

    float den = 0.f, ax = 0.f, ay = 0.f;
    for (int j0 = 0; j0 < deg; j0 += 32) {
        int j = j0 + lane;
        int s_l = cs;
        float e_l = ce;
        if (j0 > 0) {
            s_l = 0; e_l = -INFINITY;
            if (j < deg) {
                s_l = g_esrc[beg + j];
                float e = g_el[s_l * H + hd] + ern;
                e_l = (e > 0.f) ? e : NEG * e;
            }
        }
        float w_l = (j < deg) ? __expf(e_l - mx) : 0.f;
        den += w_l;
        int cnt = min(32, deg - j0);
        int j2 = 0;
        for (; j2 + 4 <= cnt; j2 += 4) {
            int s0 = __shfl_sync(0xffffffffu, s_l, j2);
            int s1 = __shfl_sync(0xffffffffu, s_l, j2 + 1);
            int s2 = __shfl_sync(0xffffffffu, s_l, j2 + 2);
            int s3 = __shfl_sync(0xffffffffu, s_l, j2 + 3);
            float w0 = __shfl_sync(0xffffffffu, w_l, j2);
            float w1 = __shfl_sync(0xffffffffu, w_l, j2 + 1);
            float w2 = __shfl_sync(0xffffffffu, w_l, j2 + 2);
            float w3 = __shfl_sync(0xffffffffu, w_l, j2 + 3);
            float2 v0 = hb[(size_t)s0 * (H * 32) + hd * 32 + lane];
            float2 v1 = hb[(size_t)s1 * (H * 32) + hd * 32 + lane];
            float2 v2 = hb[(size_t)s2 * (H * 32) + hd * 32 + lane];
            float2 v3 = hb[(size_t)s3 * (H * 32) + hd * 32 + lane];
            ax += w0 * v0.x; ay += w0 * v0.y;
            ax += w1 * v1.x; ay += w1 * v1.y;
            ax += w2 * v2.x; ay += w2 * v2.y;
            ax += w3 * v3.x; ay += w3 * v3.y;
        }
        for (; j2 < cnt; j2++) {
            int sj = __shfl_sync(0xffffffffu, s_l, j2);
            float wj = __shfl_sync(0xffffffffu, w_l, j2);
            float2 v = hb[(size_t)sj * (H * 32) + hd * 32 + lane];
            ax += wj * v.x; ay += wj * v.y;
        }
    }
    #pragma unroll
    for (int off = 16; off > 0; off >>= 1)
        den += __shfl_xor_sync(0xffffffffu, den, off);
    float inv = 1.0f / den;

    float2 o;
    o.x = ax * inv + bv.x;
    o.y = ay * inv + bv.y;
    ob[obase] = o;
}

// ---------------- generic agg (layer 2: H=1, D=47) -----------------------
template <int H, int D>
__global__ void agg_k(int selH, int selOut,
                      const float* __restrict__ bias,
                      float* __restrict__ out_ext) {
    const float* hbuf = sel_buf(selH, nullptr);
    float* out = sel_buf(selOut, out_ext);
    int w = (blockIdx.x * blockDim.x + threadIdx.x) >> 5;
    int lane = threadIdx.x & 31;
    if (w >= N_NODES * H) return;
    int n = w / H, hd = w % H;
    int beg = g_rowptr[n], end = g_rowptr[n + 1];
    int deg = end - beg;

    const int c0 = hd * D + lane;
    const int c1 = hd * D + lane + 32;

    if (deg == 0) {
        if (lane < D)                out[(size_t)n * (H * D) + c0] = bias[c0];
        if (D > 32 && lane + 32 < D) out[(size_t)n * (H * D) + c1] = bias[c1];
        return;
    }

    float ern = g_er[n * H + hd];

    float mx = -INFINITY;
    int   cs = 0;
    float ce = -INFINITY;
    for (int j0 = 0; j0 < deg; j0 += 32) {
        int j = j0 + lane;
        if (j < deg) {
            int s = g_esrc[beg + j];
            float e = g_el[s * H + hd] + ern;
            e = (e > 0.f) ? e : NEG * e;
            if (j0 == 0) { cs = s; ce = e; }
            mx = fmaxf(mx, e);
        }
    }
    #pragma unroll
    for (int off = 16; off > 0; off >>= 1)
        mx = fmaxf(mx, __shfl_xor_sync(0xffffffffu, mx, off));

    float den = 0.f, acc0 = 0.f, acc1 = 0.f;
    for (int j0 = 0; j0 < deg; j0 += 32) {
        int j = j0 + lane;
        int s_l = cs;
        float e_l = ce;
        if (j0 > 0) {
            s_l = 0; e_l = -INFINITY;
            if (j < deg) {
                s_l = g_esrc[beg + j];
                float e = g_el[s_l * H + hd] + ern;
                e_l = (e > 0.f) ? e : NEG * e;
            }
        }
        float w_l = (j < deg) ? __expf(e_l - mx) : 0.f;
        den += w_l;
        int cnt = min(32, deg - j0);
        for (int j2 = 0; j2 < cnt; j2++) {
            float wj = __shfl_sync(0xffffffffu, w_l, j2);
            int   sj = __shfl_sync(0xffffffffu, s_l, j2);
            const float* hs = hbuf + (size_t)sj * (H * D) + hd * D;
            if (lane < D)                acc0 += wj * hs[lane];
            if (D > 32 && lane + 32 < D) acc1 += wj * hs[lane + 32];
        }
    }
    #pragma unroll
    for (int off = 16; off > 0; off >>= 1)
        den += __shfl_xor_sync(0xffffffffu, den, off);
    float inv = 1.0f / den;

    if (lane < D)                out[(size_t)n * (H * D) + c0] = acc0 * inv + bias[c0];
    if (D > 32 && lane + 32 < D) out[(size_t)n * (H * D) + c1] = acc1 * inv + bias[c1];
}

// ---------------- launch (nothing but kernel launches here) ----------------
extern "C" void kernel_launch(void* const* d_in, const int* in_sizes, int n_in,
                              void* d_out, int out_size) {
    const float* x   = (const float*)d_in[0];
    const int*   src = (const int*)d_in[1];
    const int*   dst = (const int*)d_in[2];
    const float* W0  = (const float*)d_in[3];
    const float* al0 = (const float*)d_in[4];
    const float* ar0 = (const float*)d_in[5];
    const float* b0  = (const float*)d_in[6];
    const float* W1  = (const float*)d_in[7];
    const float* al1 = (const float*)d_in[8];
    const float* ar1 = (const float*)d_in[9];
    const float* b1  = (const float*)d_in[10];
    const float* W2  = (const float*)d_in[11];
    const float* al2 = (const float*)d_in[12];
    const float* ar2 = (const float*)d_in[13];
    const float* b2  = (const float*)d_in[14];
    float* out = (float*)d_out;

    const int ZB = (N_NODES + 255) / 256;
    const int EB = (N_EDGES + 255) / 256;
    const int WB4 = (N_NODES * HEADS * 32 + 255) / 256;
    const int WB1 = (N_NODES * 1 * 32 + 255) / 256;

    dim3 g256(4, (N_NODES + 127) / 128);
    dim3 g47(1, (N_NODES + 127) / 128);

    // Slot 3 (0-based) gets profiled by ncu -> layer-0 GEMM stays there.
    zero_cnt_k<<<ZB, 256>>>();                                              // 0
    hist_k<<<EB, 256>>>(dst);                                               // 1
    scan1_k<<<NBLK, 1024>>>();                                              // 2
    gemm_mma_k<<<g256, 256>>>(x, BUF_EXT, BUF_A, W0, 256, al0, ar0, HEADS); // 3 (profiled)
    scan2_k<<<1, 64>>>();                                                   // 4
    scan3_k<<<NBLK, 1024>>>();                                              // 5
    scatter_k<<<EB, 256>>>(src, dst);                                       // 6

    // layer 0 aggregation
    agg64_k<HEADS><<<WB4, 256>>>(BUF_A, BUF_B, b0);
    // layer 1
    gemm_mma_k<<<g256, 256>>>(nullptr, BUF_B, BUF_A, W1, 256, al1, ar1, HEADS);
    agg64_k<HEADS><<<WB4, 256>>>(BUF_A, BUF_B, b1);
    // layer 2 (1 head, 47 classes)
    gemm_mma_k<<<g47, 256>>>(nullptr, BUF_B, BUF_H2, W2, NCLS, al2, ar2, 1);
    agg_k<1, NCLS><<<WB1, 256>>>(BUF_H2, BUF_EXT, b2, out);
}

// round 17
// speedup vs baseline: 1.1130x; 1.0495x over previous
#include <cuda_runtime.h>
#include <cuda_fp16.h>
#include <math.h>
#include <stdint.h>

#define N_NODES 50000
#define N_EDGES 800000
#define HEADS 4
#define HIDD 64
#define NCLS 47
#define NEG 0.2f
#define NBLK 49   // ceil(50000/1024)

// ---------------- static scratch (no allocations allowed) ----------------
__device__ __align__(256) __half g_hbf[N_NODES * 256];   // fp16 h (layers 0/1)
__device__ __align__(256) float g_bufB[N_NODES * 256];   // agg output (fp32)
__device__ __align__(256) float g_h2[N_NODES * NCLS];    // layer-2 GEMM output
__device__ float g_el[N_NODES * HEADS];
__device__ float g_er[N_NODES * HEADS];
__device__ int   g_cnt[N_NODES];
__device__ int   g_rowptr[N_NODES + 1];
__device__ int   g_bsum[NBLK];
__device__ int   g_esrc[N_EDGES];

#define BUF_B   1
#define BUF_H2  2
#define BUF_EXT 3

__device__ __forceinline__ float* sel_buf(int sel, float* ext) {
    switch (sel) {
        case BUF_B:  return g_bufB;
        case BUF_H2: return g_h2;
        default:     return ext;
    }
}

// ---------------- CSR build (dst-sorted edge list) ----------------
__global__ void zero_cnt_k() {
    int i = blockIdx.x * blockDim.x + threadIdx.x;
    if (i < N_NODES) g_cnt[i] = 0;
}

__global__ void hist_k(const int* __restrict__ dst) {
    int e = blockIdx.x * blockDim.x + threadIdx.x;
    if (e < N_EDGES) atomicAdd(&g_cnt[dst[e]], 1);
}

__global__ void scan1_k() {
    __shared__ int s[1024];
    int b = blockIdx.x, tid = threadIdx.x;
    int i = b * 1024 + tid;
    int v = (i < N_NODES) ? g_cnt[i] : 0;
    s[tid] = v;
    __syncthreads();
    #pragma unroll
    for (int off = 1; off < 1024; off <<= 1) {
        int t = (tid >= off) ? s[tid - off] : 0;
        __syncthreads();
        s[tid] += t;
        __syncthreads();
    }
    if (i < N_NODES) g_rowptr[i + 1] = s[tid];
    if (tid == 1023) g_bsum[b] = s[1023];
}

__global__ void scan2_k() {
    __shared__ int s[64];
    int tid = threadIdx.x;
    int v = (tid < NBLK) ? g_bsum[tid] : 0;
    s[tid] = v;
    __syncthreads();
    #pragma unroll
    for (int off = 1; off < 64; off <<= 1) {
        int t = (tid >= off) ? s[tid - off] : 0;
        __syncthreads();
        s[tid] += t;
        __syncthreads();
    }
    if (tid < NBLK) g_bsum[tid] = s[tid] - v;   // exclusive
}

__global__ void scan3_k() {
    int b = blockIdx.x, tid = threadIdx.x;
    int i = b * 1024 + tid;
    if (i < N_NODES) {
        g_rowptr[i + 1] += g_bsum[b];
        g_cnt[i] = 0;
    }
    if (b == 0 && tid == 0) g_rowptr[0] = 0;
}

__global__ void scatter_k(const int* __restrict__ src, const int* __restrict__ dst) {
    int e = blockIdx.x * blockDim.x + threadIdx.x;
    if (e < N_EDGES) {
        int d = dst[e];
        int pos = g_rowptr[d] + atomicAdd(&g_cnt[d], 1);
        g_esrc[pos] = src[e];
    }
}

// ---------------- tensor-core GEMM + fused el/er epilogue ----------------
// EXACT R12 structure (best measured: 139.3us). For m==256 (layers 0/1) the
// C tile is written as fp16 pairs into g_hbf (halves agg gather traffic);
// el/er still computed from full-fp32 accumulators.

__device__ __forceinline__ void cvt_split_u(float x, uint32_t& hi, uint32_t& lo) {
    uint32_t h;
    asm("cvt.rna.tf32.f32 %0, %1;" : "=r"(h) : "f"(x));
    hi = h;
    lo = __float_as_uint(x - __uint_as_float(h));
}

__device__ __forceinline__ void mma8(float* c, const uint32_t* a, const uint32_t* b) {
    asm volatile(
        "mma.sync.aligned.m16n8k8.row.col.f32.tf32.tf32.f32 "
        "{%0,%1,%2,%3}, {%4,%5,%6,%7}, {%8,%9}, {%0,%1,%2,%3};"
        : "+f"(c[0]), "+f"(c[1]), "+f"(c[2]), "+f"(c[3])
        : "r"(a[0]), "r"(a[1]), "r"(a[2]), "r"(a[3]), "r"(b[0]), "r"(b[1]));
}

__device__ __forceinline__ void cp16(uint32_t dst, const float* src, int sz) {
    asm volatile("cp.async.cg.shared.global [%0], [%1], 16, %2;\n"
                 :: "r"(dst), "l"(src), "r"(sz));
}
__device__ __forceinline__ void cp4(uint32_t dst, const float* src, int sz) {
    asm volatile("cp.async.ca.shared.global [%0], [%1], 4, %2;\n"
                 :: "r"(dst), "l"(src), "r"(sz));
}

__global__ void __launch_bounds__(256, 2)
gemm_mma_k(const float* __restrict__ Aext, int selA, int selC,
           const float* __restrict__ B, int m,
           const float* __restrict__ alv, const float* __restrict__ arv, int H) {
    const float* A = (selA == BUF_EXT) ? Aext : (const float*)sel_buf(selA, nullptr);
    float* C = sel_buf(selC, nullptr);

    __shared__ float As[2][128][20];
    __shared__ float Bs[2][16][72];
    __shared__ float els[128], ers[128];

    int t = threadIdx.x;
    int warp = t >> 5, lane = t & 31;
    int wm = warp >> 1, wn = warp & 1;
    int g = lane >> 2, tq = lane & 3;
    int rowBlk = blockIdx.y * 128;
    int hd = blockIdx.x;
    int colBlk = hd * 64;

    float c[2][4][4] = {};

    int ar0_ = t >> 2;
    int ak0_ = (t & 3) * 4;
    int ar1_ = (t + 256) >> 2;
    int ak1_ = ak0_;
    int bkb = t >> 4, bcc = (t & 15) * 4;

    #define PREFETCH(kt, buf)                                                      \
    {                                                                              \
        int rA0 = rowBlk + ar0_, rA1 = rowBlk + ar1_;                              \
        cp16((uint32_t)__cvta_generic_to_shared(&As[buf][ar0_][ak0_]),             \
             A + (size_t)min(rA0, N_NODES - 1) * 256 + (kt) + ak0_,                \
             rA0 < N_NODES ? 16 : 0);                                              \
        cp16((uint32_t)__cvta_generic_to_shared(&As[buf][ar1_][ak1_]),             \
             A + (size_t)min(rA1, N_NODES - 1) * 256 + (kt) + ak1_,                \
             rA1 < N_NODES ? 16 : 0);                                              \
        if (m == 256) {                                                            \
            cp16((uint32_t)__cvta_generic_to_shared(&Bs[buf][bkb][bcc]),           \
                 B + (size_t)((kt) + bkb) * 256 + colBlk + bcc, 16);               \
        } else {                                                                   \
            _Pragma("unroll")                                                      \
            for (int p = 0; p < 4; p++) {                                          \
                int id = t + p * 256;                                              \
                int kb = id >> 6, cc = id & 63;                                    \
                int col = colBlk + cc;                                             \
                cp4((uint32_t)__cvta_generic_to_shared(&Bs[buf][kb][cc]),          \
                    B + (size_t)((kt) + kb) * m + min(col, m - 1),                 \
                    col < m ? 4 : 0);                                              \
            }                                                                      \
        }                                                                          \
        asm volatile("cp.async.commit_group;\n");                                  \
    }

    PREFETCH(0, 0);

    for (int i = 0; i < 16; i++) {
        int buf = i & 1;
        if (i < 15) {
            PREFETCH((i + 1) * 16, buf ^ 1);
            asm volatile("cp.async.wait_group 1;\n");
        } else {
            asm volatile("cp.async.wait_group 0;\n");
        }
        __syncthreads();

        #pragma unroll
        for (int ks = 0; ks < 16; ks += 8) {
            uint32_t bh[4][2], bl[4][2];
            #pragma unroll
            for (int nt = 0; nt < 4; nt++) {
                int col = wn * 32 + nt * 8 + g;
                cvt_split_u(Bs[buf][ks + tq][col],     bh[nt][0], bl[nt][0]);
                cvt_split_u(Bs[buf][ks + tq + 4][col], bh[nt][1], bl[nt][1]);
            }
            #pragma unroll
            for (int mt = 0; mt < 2; mt++) {
                int r0 = wm * 32 + mt * 16 + g;
                uint32_t ah[4], al_[4];
                cvt_split_u(As[buf][r0][ks + tq],         ah[0], al_[0]);
                cvt_split_u(As[buf][r0 + 8][ks + tq],     ah[1], al_[1]);
                cvt_split_u(As[buf][r0][ks + tq + 4],     ah[2], al_[2]);
                cvt_split_u(As[buf][r0 + 8][ks + tq + 4], ah[3], al_[3]);
                #pragma unroll
                for (int nt = 0; nt < 4; nt++) {
                    mma8(c[mt][nt], ah,  bh[nt]);
                    mma8(c[mt][nt], ah,  bl[nt]);
                    mma8(c[mt][nt], al_, bh[nt]);
                }
            }
        }
        __syncthreads();
    }

    // store C: m==256 -> fp16 pairs into g_hbf; else fp32 guarded
    if (m == 256) {
        __half2* hb2 = (__half2*)g_hbf;
        #pragma unroll
        for (int mt = 0; mt < 2; mt++) {
            #pragma unroll
            for (int nt = 0; nt < 4; nt++) {
                int row = rowBlk + wm * 32 + mt * 16 + g;
                int col = colBlk + wn * 32 + nt * 8 + tq * 2;
                if (row < N_NODES)
                    hb2[((size_t)row * 256 + col) >> 1] =
                        __floats2half2_rn(c[mt][nt][0], c[mt][nt][1]);
                if (row + 8 < N_NODES)
                    hb2[((size_t)(row + 8) * 256 + col) >> 1] =
                        __floats2half2_rn(c[mt][nt][2], c[mt][nt][3]);
            }
        }
    } else {
        #pragma unroll
        for (int mt = 0; mt < 2; mt++) {
            #pragma unroll
            for (int nt = 0; nt < 4; nt++) {
                int row = rowBlk + wm * 32 + mt * 16 + g;
                int col = colBlk + wn * 32 + nt * 8 + tq * 2;
                if (row < N_NODES) {
                    if (col < m)     C[(size_t)row * m + col]     = c[mt][nt][0];
                    if (col + 1 < m) C[(size_t)row * m + col + 1] = c[mt][nt][1];
                }
                if (row + 8 < N_NODES) {
                    if (col < m)     C[(size_t)(row + 8) * m + col]     = c[mt][nt][2];
                    if (col + 1 < m) C[(size_t)(row + 8) * m + col + 1] = c[mt][nt][3];
                }
            }
        }
    }

    // fused el/er epilogue (from fp32 accumulators)
    if (t < 128) { els[t] = 0.f; ers[t] = 0.f; }
    __syncthreads();
    #pragma unroll
    for (int mt = 0; mt < 2; mt++) {
        float pe0 = 0.f, pr0 = 0.f, pe1 = 0.f, pr1 = 0.f;
        #pragma unroll
        for (int nt = 0; nt < 4; nt++) {
            #pragma unroll
            for (int j = 0; j < 2; j++) {
                int colg = colBlk + wn * 32 + nt * 8 + tq * 2 + j;
                float av = (colg < m) ? alv[colg] : 0.f;
                float rv = (colg < m) ? arv[colg] : 0.f;
                pe0 += c[mt][nt][j] * av;     pr0 += c[mt][nt][j] * rv;
                pe1 += c[mt][nt][2 + j] * av; pr1 += c[mt][nt][2 + j] * rv;
            }
        }
        #pragma unroll
        for (int off = 1; off <= 2; off <<= 1) {
            pe0 += __shfl_xor_sync(0xffffffffu, pe0, off);
            pr0 += __shfl_xor_sync(0xffffffffu, pr0, off);
            pe1 += __shfl_xor_sync(0xffffffffu, pe1, off);
            pr1 += __shfl_xor_sync(0xffffffffu, pr1, off);
        }
        if (tq == 0) {
            int rl = wm * 32 + mt * 16 + g;
            atomicAdd(&els[rl], pe0);     atomicAdd(&ers[rl], pr0);
            atomicAdd(&els[rl + 8], pe1); atomicAdd(&ers[rl + 8], pr1);
        }
    }
    __syncthreads();
    if (t < 128) {
        int row = rowBlk + t;
        if (row < N_NODES) {
            g_el[row * H + hd] = els[t];
            g_er[row * H + hd] = ers[t];
        }
    }
}

// ---------------- D=64 agg: fp16x2 gather, unroll-4 broadcast -------------
// Gathers fp16 features from g_hbf (half the L2 traffic of fp32), accumulates
// in fp32, writes fp32 to g_bufB.
template <int H>
__global__ void agg64_k(const float* __restrict__ bias) {
    const __half2* hb = (const __half2*)g_hbf;
    float2* ob = (float2*)g_bufB;
    int w = (blockIdx.x * blockDim.x + threadIdx.x) >> 5;
    int lane = threadIdx.x & 31;
    if (w >= N_NODES * H) return;
    int n = w / H, hd = w % H;
    int beg = g_rowptr[n], end = g_rowptr[n + 1];
    int deg = end - beg;

    const float2* bias2 = (const float2*)bias;
    float2 bv = bias2[hd * 32 + lane];
    size_t obase = (size_t)n * (H * 32) + hd * 32 + lane;

    if (deg == 0) { ob[obase] = bv; return; }

    float ern = g_er[n * H + hd];

    // pass 1: warp max (+ cache first chunk)
    float mx = -INFINITY;
    int   cs = 0;
    float ce = -INFINITY;
    for (int j0 = 0; j0 < deg; j0 += 32) {
        int j = j0 + lane;
        if (j < deg) {
            int s = g_esrc[beg + j];
            float e = g_el[s * H + hd] + ern;
            e = (e > 0.f) ? e : NEG * e;
            if (j0 == 0) { cs = s; ce = e; }
            mx = fmaxf(mx, e);
        }
    }
    #pragma unroll
    for (int off = 16; off > 0; off >>= 1)
        mx = fmaxf(mx, __shfl_xor_sync(0xffffffffu, mx, off));

    // pass 2: unnormalized accumulate, 4-way unrolled broadcast
    float den = 0.f, ax = 0.f, ay = 0.f;
    for (int j0 = 0; j0 < deg; j0 += 32) {
        int j = j0 + lane;
        int s_l = cs;
        float e_l = ce;
        if (j0 > 0) {
            s_l = 0; e_l = -INFINITY;
            if (j < deg) {
                s_l = g_esrc[beg + j];
                float e = g_el[s_l * H + hd] + ern;
                e_l = (e > 0.f) ? e : NEG * e;
            }
        }
        float w_l = (j < deg) ? __expf(e_l - mx) : 0.f;
        den += w_l;
        int cnt = min(32, deg - j0);
        int j2 = 0;
        for (; j2 + 4 <= cnt; j2 += 4) {
            int s0 = __shfl_sync(0xffffffffu, s_l, j2);
            int s1 = __shfl_sync(0xffffffffu, s_l, j2 + 1);
            int s2 = __shfl_sync(0xffffffffu, s_l, j2 + 2);
            int s3 = __shfl_sync(0xffffffffu, s_l, j2 + 3);
            float w0 = __shfl_sync(0xffffffffu, w_l, j2);
            float w1 = __shfl_sync(0xffffffffu, w_l, j2 + 1);
            float w2 = __shfl_sync(0xffffffffu, w_l, j2 + 2);
            float w3 = __shfl_sync(0xffffffffu, w_l, j2 + 3);
            float2 f0 = __half22float2(hb[(size_t)s0 * (H * 32) + hd * 32 + lane]);
            float2 f1 = __half22float2(hb[(size_t)s1 * (H * 32) + hd * 32 + lane]);
            float2 f2 = __half22float2(hb[(size_t)s2 * (H * 32) + hd * 32 + lane]);
            float2 f3 = __half22float2(hb[(size_t)s3 * (H * 32) + hd * 32 + lane]);
            ax += w0 * f0.x; ay += w0 * f0.y;
            ax += w1 * f1.x; ay += w1 * f1.y;
            ax += w2 * f2.x; ay += w2 * f2.y;
            ax += w3 * f3.x; ay += w3 * f3.y;
        }
        for (; j2 < cnt; j2++) {
            int sj = __shfl_sync(0xffffffffu, s_l, j2);
            float wj = __shfl_sync(0xffffffffu, w_l, j2);
            float2 f = __half22float2(hb[(size_t)sj * (H * 32) + hd * 32 + lane]);
            ax += wj * f.x; ay += wj * f.y;
        }
    }
    #pragma unroll
    for (int off = 16; off > 0; off >>= 1)
        den += __shfl_xor_sync(0xffffffffu, den, off);
    float inv = 1.0f / den;

    float2 o;
    o.x = ax * inv + bv.x;
    o.y = ay * inv + bv.y;
    ob[obase] = o;
}

// ---------------- generic agg (layer 2: H=1, D=47, fp32 h2) --------------
template <int H, int D>
__global__ void agg_k(int selH, int selOut,
                      const float* __restrict__ bias,
                      float* __restrict__ out_ext) {
    const float* hbuf = sel_buf(selH, nullptr);
    float* out = sel_buf(selOut, out_ext);
    int w = (blockIdx.x * blockDim.x + threadIdx.x) >> 5;
    int lane = threadIdx.x & 31;
    if (w >= N_NODES * H) return;
    int n = w / H, hd = w % H;
    int beg = g_rowptr[n], end = g_rowptr[n + 1];
    int deg = end - beg;

    const int c0 = hd * D + lane;
    const int c1 = hd * D + lane + 32;

    if (deg == 0) {
        if (lane < D)                out[(size_t)n * (H * D) + c0] = bias[c0];
        if (D > 32 && lane + 32 < D) out[(size_t)n * (H * D) + c1] = bias[c1];
        return;
    }

    float ern = g_er[n * H + hd];

    float mx = -INFINITY;
    int   cs = 0;
    float ce = -INFINITY;
    for (int j0 = 0; j0 < deg; j0 += 32) {
        int j = j0 + lane;
        if (j < deg) {
            int s = g_esrc[beg + j];
            float e = g_el[s * H + hd] + ern;
            e = (e > 0.f) ? e : NEG * e;
            if (j0 == 0) { cs = s; ce = e; }
            mx = fmaxf(mx, e);
        }
    }
    #pragma unroll
    for (int off = 16; off > 0; off >>= 1)
        mx = fmaxf(mx, __shfl_xor_sync(0xffffffffu, mx, off));

    float den = 0.f, acc0 = 0.f, acc1 = 0.f;
    for (int j0 = 0; j0 < deg; j0 += 32) {
        int j = j0 + lane;
        int s_l = cs;
        float e_l = ce;
        if (j0 > 0) {
            s_l = 0; e_l = -INFINITY;
            if (j < deg) {
                s_l = g_esrc[beg + j];
                float e = g_el[s_l * H + hd] + ern;
                e_l = (e > 0.f) ? e : NEG * e;
            }
        }
        float w_l = (j < deg) ? __expf(e_l - mx) : 0.f;
        den += w_l;
        int cnt = min(32, deg - j0);
        for (int j2 = 0; j2 < cnt; j2++) {
            float wj = __shfl_sync(0xffffffffu, w_l, j2);
            int   sj = __shfl_sync(0xffffffffu, s_l, j2);
            const float* hs = hbuf + (size_t)sj * (H * D) + hd * D;
            if (lane < D)                acc0 += wj * hs[lane];
            if (D > 32 && lane + 32 < D) acc1 += wj * hs[lane + 32];
        }
    }
    #pragma unroll
    for (int off = 16; off > 0; off >>= 1)
        den += __shfl_xor_sync(0xffffffffu, den, off);
    float inv = 1.0f / den;

    if (lane < D)                out[(size_t)n * (H * D) + c0] = acc0 * inv + bias[c0];
    if (D > 32 && lane + 32 < D) out[(size_t)n * (H * D) + c1] = acc1 * inv + bias[c1];
}

// ---------------- launch (nothing but kernel launches here) ----------------
extern "C" void kernel_launch(void* const* d_in, const int* in_sizes, int n_in,
                              void* d_out, int out_size) {
    const float* x   = (const float*)d_in[0];
    const int*   src = (const int*)d_in[1];
    const int*   dst = (const int*)d_in[2];
    const float* W0  = (const float*)d_in[3];
    const float* al0 = (const float*)d_in[4];
    const float* ar0 = (const float*)d_in[5];
    const float* b0  = (const float*)d_in[6];
    const float* W1  = (const float*)d_in[7];
    const float* al1 = (const float*)d_in[8];
    const float* ar1 = (const float*)d_in[9];
    const float* b1  = (const float*)d_in[10];
    const float* W2  = (const float*)d_in[11];
    const float* al2 = (const float*)d_in[12];
    const float* ar2 = (const float*)d_in[13];
    const float* b2  = (const float*)d_in[14];
    float* out = (float*)d_out;

    const int ZB = (N_NODES + 255) / 256;
    const int EB = (N_EDGES + 255) / 256;
    const int WB4 = (N_NODES * HEADS * 32 + 255) / 256;
    const int WB1 = (N_NODES * 1 * 32 + 255) / 256;

    dim3 g256(4, (N_NODES + 127) / 128);
    dim3 g47(1, (N_NODES + 127) / 128);

    // Slot 3 (0-based) gets profiled by ncu -> layer-0 GEMM stays there.
    zero_cnt_k<<<ZB, 256>>>();                                              // 0
    hist_k<<<EB, 256>>>(dst);                                               // 1
    scan1_k<<<NBLK, 1024>>>();                                              // 2
    gemm_mma_k<<<g256, 256>>>(x, BUF_EXT, BUF_B, W0, 256, al0, ar0, HEADS); // 3 (writes g_hbf)
    scan2_k<<<1, 64>>>();                                                   // 4
    scan3_k<<<NBLK, 1024>>>();                                              // 5
    scatter_k<<<EB, 256>>>(src, dst);                                       // 6

    // layer 0 aggregation: g_hbf (fp16) -> g_bufB (fp32)
    agg64_k<HEADS><<<WB4, 256>>>(b0);
    // layer 1: g_bufB -> g_hbf (fp16) ; agg -> g_bufB
    gemm_mma_k<<<g256, 256>>>(nullptr, BUF_B, BUF_B, W1, 256, al1, ar1, HEADS);
    agg64_k<HEADS><<<WB4, 256>>>(b1);
    // layer 2 (1 head, 47 classes): fp32 path
    gemm_mma_k<<<g47, 256>>>(nullptr, BUF_B, BUF_H2, W2, NCLS, al2, ar2, 1);
    agg_k<1, NCLS><<<WB1, 256>>>(BUF_H2, BUF_EXT, b2, out);
}